// round 11
// baseline (speedup 1.0000x reference)
#include <cuda_runtime.h>

// ReNet layer, R10: k-split hybrid. 512 thr = 4 seq-groups x 2 k-halves x
// 2 hid-halves. M=8 seqs/warp (minimal weight-read redundancy: 48 crossbar
// cyc/k < 64 FMA cyc/k) AND 4 warps/SMSP (latency hiding). Single-buffered
// GEMM (reg cap 128 @ 512thr). k-half partials combined via two-round
// gate-pair smem exchange in the group x-region (horiz) / dedicated buffer
// (vert). Group-local reused named barrier, 5-6 syncs/step (~3% of GEMM).

#define HIDN 64
#define NGC  256
#define BN   16
#define SJ   128
#define NSEQ 32
#define NTHR 512

typedef unsigned long long ull;

__device__ float g_v[BN * SJ * SJ * 2 * HIDN];   // vertical output [B][J][I][128]

__device__ __forceinline__ ull pack2(float lo, float hi) {
    ull r; asm("mov.b64 %0, {%1, %2};" : "=l"(r) : "f"(lo), "f"(hi)); return r;
}
__device__ __forceinline__ void unpack2(ull v, float& lo, float& hi) {
    asm("mov.b64 {%0, %1}, %2;" : "=f"(lo), "=f"(hi) : "l"(v));
}
__device__ __forceinline__ void ffma2(ull& d, ull a, ull b) {
    asm("fma.rn.f32x2 %0, %1, %2, %0;" : "+l"(d) : "l"(a), "l"(b));
}
__device__ __forceinline__ ull addf2(ull a, ull b) {
    ull r; asm("add.rn.f32x2 %0, %1, %2;" : "=l"(r) : "l"(a), "l"(b)); return r;
}
__device__ __forceinline__ float sigf(float x)   { return 1.0f / (1.0f + __expf(-x)); }
__device__ __forceinline__ float mytanh(float x) { return 1.0f - 2.0f / (__expf(2.0f * x) + 1.0f); }
__device__ __forceinline__ void bar_grp(int sg) {
    asm volatile("bar.sync %0, 128;" :: "r"(sg + 1) : "memory");
}

template <int DIN>
__global__ void __launch_bounds__(NTHR, 1)
renet_pass(const float* __restrict__ W0, const float* __restrict__ U0, const float* __restrict__ b0,
           const float* __restrict__ W1, const float* __restrict__ U1, const float* __restrict__ b1,
           const float* __restrict__ src, float* __restrict__ dst)
{
    constexpr int K  = DIN + HIDN;
    constexpr int KP = (K + 7) & ~7;          // padded (zero weights / zero x pad)
    constexpr int KH = KP / 2;                // per-warp K half (40 / 96), %8==0... 40%8=0 ✓
    extern __shared__ float sm[];
    float* sWU = sm;                   // [KP][NGC]  combined W;U, gate-pair layout
    float* sXH = sm + KP * NGC;        // [NSEQ][KP] per-seq (x_t ++ h ++ pad)
    float* sB  = sXH + NSEQ * KP;      // [NGC]
    float* sP  = sB + NGC;             // [NSEQ][128] partial buffer (vertical only)

    const int dir  = blockIdx.x >> 6;
    const int s0   = (blockIdx.x & 63) * NSEQ;
    const int tid  = threadIdx.x;
    const int lane = tid & 31;
    const int wid  = tid >> 5;
    const int hh   = wid & 1;                 // hid half
    const int kh   = (wid >> 1) & 1;          // k half
    const int sg   = wid >> 2;                // seq group (8 seqs), 0..3
    const int hid  = hh * 32 + lane;

    const float* W  = dir ? W1 : W0;
    const float* U  = dir ? U1 : U0;
    const float* bb = dir ? b1 : b0;

    // weight layout: sWU[k][ (h>>5)*128 + (h&31)*4 + g ] = orig[k][g*64 + h]
    // -> per (warp,k): LDS.128 at lane*16B, conflict-free; float4 = (wi,wf,wg,wo)
    for (int idx = tid; idx < KP * NGC; idx += NTHR) {
        int k = idx >> 8, c = idx & 255;
        int g = c >> 6, h = c & 63;
        int pc = (h >> 5) * 128 + (h & 31) * 4 + g;
        float v = (k < DIN) ? W[k * NGC + c]
                 : (k < K)  ? U[(k - DIN) * NGC + c] : 0.0f;
        sWU[k * NGC + pc] = v;
    }
    for (int idx = tid; idx < NGC; idx += NTHR) sB[idx] = bb[idx];
    for (int idx = tid; idx < NSEQ * (KP - DIN); idx += NTHR) {
        int s = idx / (KP - DIN), o = idx % (KP - DIN);
        sXH[s * KP + DIN + o] = 0.0f;          // h_0 = 0 and k-pad = 0
    }
    __syncthreads();

    ull binit[2];                              // bias folded into kh==0 partials
    binit[0] = kh ? 0ull : pack2(sB[0 * HIDN + hid], sB[1 * HIDN + hid]);
    binit[1] = kh ? 0ull : pack2(sB[2 * HIDN + hid], sB[3 * HIDN + hid]);

    float cst[8];                              // used by kh==0 warps
#pragma unroll
    for (int p = 0; p < 8; p++) cst[p] = 0.0f;

    // ---- x staging by the group's kh==1 warps (64 threads: hh*32+lane)
    auto stage_x = [&](int t) {
        const int xt = tid & 63;               // == hh*32+lane for kh fixed
        if (DIN == 12) {
            const int jin = dir ? (SJ - 1 - t) : t;
            for (int e = xt; e < 8 * 12; e += 64) {
                int sl = e / 12, d = e - sl * 12;
                int q = s0 + sg * 8 + sl;
                int b = q >> 7, i = q & 127;
                int pr = d / 6, rm = d - pr * 6;
                int pc = rm / 3, ch = rm - pc * 3;
                sXH[(sg * 8 + sl) * KP + d] =
                    src[((b * 256 + (2 * jin + pr)) * 256 + (2 * i + pc)) * 3 + ch];
            }
        } else {
            const int iin = dir ? (SJ - 1 - t) : t;
#pragma unroll
            for (int r = 0; r < 4; r++) {
                int idx = xt + 64 * r;         // 256 = 8 seq * 32 float4
                int sl = idx >> 5, f4 = idx & 31;
                int q = s0 + sg * 8 + sl;
                int b = q >> 7, j = q & 127;
                float4 v4 = *(const float4*)
                    &src[((size_t)((b * 128 + j) * 128 + iin)) * 128 + f4 * 4];
                *(float4*)&sXH[(sg * 8 + sl) * KP + f4 * 4] = v4;
            }
        }
    };

    if (kh == 1) stage_x(0);

    const float* xbase = sXH + (sg * 8) * KP;
    const float* wbase = sWU + hh * 128 + lane * 4;
    const int    kbeg  = kh * KH;
    // partial-exchange buffer: vertical -> sP; horizontal -> group's x-region
    float* rbuf   = (DIN == 12) ? (sP + (sg * 8) * 128) : (sXH + (sg * 8) * KP);
    const int RS  = (DIN == 12) ? 128 : KP;
    float* rlane  = rbuf + hid * 2;

    for (int t = 0; t < SJ; t++) {
        bar_grp(sg);                           // 1: x_t staged, h_{t-1} visible

        ull acc[8][2];
#pragma unroll
        for (int m = 0; m < 8; m++) {
            acc[m][0] = binit[0];
            acc[m][1] = binit[1];
        }

#pragma unroll 2
        for (int k = kbeg; k < kbeg + KH; k += 4) {
            float4 xq[8];
            ulonglong2 wq[4];
#pragma unroll
            for (int m = 0; m < 8; m++) xq[m] = *(const float4*)&xbase[m * KP + k];
#pragma unroll
            for (int kk = 0; kk < 4; kk++)
                wq[kk] = *(const ulonglong2*)(wbase + (k + kk) * NGC);
#pragma unroll
            for (int kk = 0; kk < 4; kk++) {
#pragma unroll
                for (int m = 0; m < 8; m++) {
                    float a = ((const float*)&xq[m])[kk];
                    ull a2 = pack2(a, a);
                    ffma2(acc[m][0], a2, wq[kk].x);   // (zi, zf)
                    ffma2(acc[m][1], a2, wq[kk].y);   // (zg, zo)
                }
            }
        }

        bar_grp(sg);                           // 2: GEMM reads done; rbuf free

        if (kh == 1) {                         // round A: (zi,zf) partials
#pragma unroll
            for (int m = 0; m < 8; m++)
                *(ull*)(rlane + m * RS) = acc[m][0];
        }
        bar_grp(sg);                           // 3: round A stored
        if (kh == 0) {
#pragma unroll
            for (int m = 0; m < 8; m++)
                acc[m][0] = addf2(acc[m][0], *(const ull*)(rlane + m * RS));
        }
        bar_grp(sg);                           // 4: round A consumed
        if (kh == 1) {                         // round B: (zg,zo) partials
#pragma unroll
            for (int m = 0; m < 8; m++)
                *(ull*)(rlane + m * RS) = acc[m][1];
        }
        bar_grp(sg);                           // 5: round B stored
        if (kh == 0) {
#pragma unroll
            for (int m = 0; m < 8; m++)
                acc[m][1] = addf2(acc[m][1], *(const ull*)(rlane + m * RS));
        }
        if (DIN != 12) bar_grp(sg);            // 6: round B reads done (horiz:
                                               //    x-region doubles as rbuf)
        if (kh == 0) {
            // ---- gates, state update, h write-back + global store
#pragma unroll
            for (int m = 0; m < 8; m++) {
                float zi, zf, zg, zo;
                unpack2(acc[m][0], zi, zf);
                unpack2(acc[m][1], zg, zo);
                float c = sigf(zf) * cst[m] + sigf(zi) * mytanh(zg);
                cst[m] = c;
                float hv = sigf(zo) * mytanh(c);

                int s = sg * 8 + m;
                sXH[s * KP + DIN + hid] = hv;

                int q = s0 + s;
                int b = q >> 7, w = q & 127;
                int row = (DIN == 12) ? t : w;
                int col = (DIN == 12) ? w : t;
                dst[((size_t)((b * 128 + row) * 128 + col)) * 128 + dir * 64 + hid] = hv;
            }
        } else {
            if (t + 1 < SJ) stage_x(t + 1);
        }
    }
}

extern "C" void kernel_launch(void* const* d_in, const int* in_sizes, int n_in,
                              void* d_out, int out_size)
{
    const float* inputs = (const float*)d_in[0];
    const float* W_ud = (const float*)d_in[1];
    const float* U_ud = (const float*)d_in[2];
    const float* b_ud = (const float*)d_in[3];
    const float* W_du = (const float*)d_in[4];
    const float* U_du = (const float*)d_in[5];
    const float* b_du = (const float*)d_in[6];
    const float* W_lr = (const float*)d_in[7];
    const float* U_lr = (const float*)d_in[8];
    const float* b_lr = (const float*)d_in[9];
    const float* W_rl = (const float*)d_in[10];
    const float* U_rl = (const float*)d_in[11];
    const float* b_rl = (const float*)d_in[12];

    float* vbuf = nullptr;
    cudaGetSymbolAddress((void**)&vbuf, g_v);

    constexpr int KP1 = 80;    // (12+64) padded to 8
    constexpr int KP2 = 192;   // 128+64
    // vertical: + dedicated 16KB partial buffer; horizontal aliases x-region
    size_t smem1 = (size_t)(KP1 * NGC + NSEQ * KP1 + NGC + NSEQ * 128) * sizeof(float); // 109,568
    size_t smem2 = (size_t)(KP2 * NGC + NSEQ * KP2 + NGC) * sizeof(float);              // 222,208

    cudaFuncSetAttribute(renet_pass<12>,  cudaFuncAttributeMaxDynamicSharedMemorySize, (int)smem1);
    cudaFuncSetAttribute(renet_pass<128>, cudaFuncAttributeMaxDynamicSharedMemorySize, (int)smem2);

    renet_pass<12><<<128, NTHR, smem1>>>(W_ud, U_ud, b_ud, W_du, U_du, b_du,
                                         inputs, vbuf);
    renet_pass<128><<<128, NTHR, smem2>>>(W_lr, U_lr, b_lr, W_rl, U_rl, b_rl,
                                          vbuf, (float*)d_out);
}